// round 2
// baseline (speedup 1.0000x reference)
#include <cuda_runtime.h>
#include <math.h>

// Problem geometry (fixed by the reference's setup_inputs)
#define NB 2
#define FH 1080
#define FW 1920
#define SH 540
#define SW 960

#define NSMALL (NB*SH*SW)
#define NBIG   (NB*FH*FW)

// Fractional pixel shifts: offset * (W-1)/W
#define S1 (959.0f/960.0f)     // sobel_offset=1.0, x, W=960
#define S2 (959.0f/1920.0f)    // kernel_offset=0.5, x, W=960
#define T1 (539.0f/540.0f)     // sobel_offset=1.0, y, H=540
#define T2 (539.0f/1080.0f)    // kernel_offset=0.5, y, H=540

// apply_warp step in pixel units: relstr * (dim-1)/dim, relstr = 0.1
#define STEPX (0.1f * 1919.0f/1920.0f)
#define STEPY (0.1f * 1079.0f/1080.0f)

// coarse<->full mapping (align_corners)
#define SXC (959.0f/1919.0f)
#define SYC (539.0f/1079.0f)

// Gaussian sigma=1.0, ks=5
#define GW0 0.05448868454964295f
#define GW1 0.24420134200323332f
#define GW2 0.4026199468942475f

// ---- scratch (static device memory; no allocations) ----
__device__ float  g_luma[NSMALL];
__device__ float  g_edge[NSMALL];
__device__ float  g_blur[NSMALL];
__device__ float2 g_gs  [NSMALL];

__device__ __forceinline__ float clampf(float v, float lo, float hi) {
    return fminf(fmaxf(v, lo), hi);
}

// ---- 1. fused luma + bilinear resize 1080x1920 -> 540x960 ----
__global__ void k_luma_resize(const float* __restrict__ img) {
    int idx = blockIdx.x * blockDim.x + threadIdx.x;
    if (idx >= NSMALL) return;
    int x = idx % SW;
    int y = (idx / SW) % SH;
    int b = idx / (SW * SH);

    float px = clampf((float)x * (1919.0f / 959.0f), 0.0f, 1919.0f);
    float py = clampf((float)y * (1079.0f / 539.0f), 0.0f, 1079.0f);
    float x0f = floorf(px), y0f = floorf(py);
    int i0 = (int)x0f, j0 = (int)y0f;
    int i1 = min(i0 + 1, FW - 1), j1 = min(j0 + 1, FH - 1);
    float wx = px - x0f, wy = py - y0f;

    const float* r = img + (size_t)b * 3 * FH * FW;
    const float* g = r + FH * FW;
    const float* bb = g + FH * FW;

    int o00 = j0 * FW + i0, o01 = j0 * FW + i1, o10 = j1 * FW + i0, o11 = j1 * FW + i1;
    float v00 = 0.299f * r[o00] + 0.587f * g[o00] + 0.114f * bb[o00];
    float v01 = 0.299f * r[o01] + 0.587f * g[o01] + 0.114f * bb[o01];
    float v10 = 0.299f * r[o10] + 0.587f * g[o10] + 0.114f * bb[o10];
    float v11 = 0.299f * r[o11] + 0.587f * g[o11] + 0.114f * bb[o11];

    g_luma[idx] = (v00 * (1.0f - wx) + v01 * wx) * (1.0f - wy)
                + (v10 * (1.0f - wx) + v11 * wx) * wy;
}

// sobel_x for one row given 3 clamped taps (L=clamp(x-1), C=x, R=clamp(x+1)).
// Interior interpolation formulas are exact at the borders because the clamped
// taps coincide (L==C at x=0, R==C at x=W-1) and the degenerate weight is 0.
__device__ __forceinline__ float2 sobelx_row(float L, float C, float R, float s, int x, int W) {
    float xs = fmaxf((float)x - s, 0.0f);               // <= W-1 automatically
    float wl = xs - floorf(xs);
    float l = L * (1.0f - wl) + C * wl;                 // taps (x-1, x)
    float xs2 = fminf((float)x + s, (float)(W - 1));
    float wr = xs2 - floorf(xs2);
    float r = C * (1.0f - wr) + R * wr;                 // taps (x, x+1)
    return make_float2(r - l, l + 2.0f * C + r);
}

// ---- 2/4. fused sobel_x + sobel_y over a 3x3 clamped footprint ----
template<bool MAG>
__global__ void k_sobel() {
    int idx = blockIdx.x * blockDim.x + threadIdx.x;
    if (idx >= NSMALL) return;
    const float* src = MAG ? g_luma : g_blur;
    const float s = MAG ? S1 : S2;
    const float t = MAG ? T1 : T2;

    int x = idx % SW;
    int y = (idx / SW) % SH;
    int b = idx / (SW * SH);
    const float* plane = src + b * SH * SW;

    int xm = max(x - 1, 0), xp = min(x + 1, SW - 1);
    int ym = max(y - 1, 0), yp = min(y + 1, SH - 1);

    const float* r0 = plane + ym * SW;
    const float* r1 = plane + y  * SW;
    const float* r2 = plane + yp * SW;

    float2 s0 = sobelx_row(r0[xm], r0[x], r0[xp], s, x, SW);
    float2 s1 = sobelx_row(r1[xm], r1[x], r1[xp], s, x, SW);
    float2 s2 = sobelx_row(r2[xm], r2[x], r2[xp], s, x, SW);

    // top = sample at y - t : taps rows (y-1, y)
    float ys = fmaxf((float)y - t, 0.0f);
    float wt = ys - floorf(ys);
    float2 top = make_float2(s0.x * (1.0f - wt) + s1.x * wt,
                             s0.y * (1.0f - wt) + s1.y * wt);
    // bot = sample at y + t : taps rows (y, y+1)
    float ys2 = fminf((float)y + t, (float)(SH - 1));
    float wb = ys2 - floorf(ys2);
    float2 bot = make_float2(s1.x * (1.0f - wb) + s2.x * wb,
                             s1.y * (1.0f - wb) + s2.y * wb);

    float xg = (top.x + 2.0f * s1.x + bot.x) * 0.125f;
    float yg = (bot.y - top.y) * 0.125f;

    if (MAG) {
        g_edge[idx] = powf(xg * xg + yg * yg, 0.35f);   // sqrt(.)^0.7
    } else {
        g_gs[idx] = make_float2(xg, yg);
    }
}

// ---- 3. fused separable 5x5 gaussian, replicate padding ----
__global__ void k_blur() {
    int idx = blockIdx.x * blockDim.x + threadIdx.x;
    if (idx >= NSMALL) return;
    int x = idx % SW;
    int y = (idx / SW) % SH;
    int b = idx / (SW * SH);
    const float* plane = g_edge + b * SH * SW;

    int xs[5] = { max(x - 2, 0), max(x - 1, 0), x, min(x + 1, SW - 1), min(x + 2, SW - 1) };
    int yrow[5] = { max(y - 2, 0), max(y - 1, 0), y, min(y + 1, SH - 1), min(y + 2, SH - 1) };

    float h[5];
    #pragma unroll
    for (int m = 0; m < 5; ++m) {
        const float* row = plane + yrow[m] * SW;
        h[m] = GW0 * row[xs[0]] + GW1 * row[xs[1]] + GW2 * row[xs[2]]
             + GW1 * row[xs[3]] + GW0 * row[xs[4]];
    }
    g_blur[idx] = GW0 * h[0] + GW1 * h[1] + GW2 * h[2] + GW1 * h[3] + GW0 * h[4];
}

// ---- 5. warp: fused upsample (register 3x3 full-res grad) + 6-iter walk + gather ----
__global__ void __launch_bounds__(256) k_warp(const float* __restrict__ img,
                                              float* __restrict__ out) {
    int idx = blockIdx.x * blockDim.x + threadIdx.x;
    if (idx >= NBIG) return;
    int x = idx % FW;
    int y = (idx / FW) % FH;
    int b = idx / (FW * FH);

    // --- build gf[3][3]: full-res grad field at integer cols {x-1,x,x+1}, rows {y-1,y,y+1} (clamped)
    int ixm = max(x - 1, 0), ixp = min(x + 1, FW - 1);
    int jym = max(y - 1, 0), jyp = min(y + 1, FH - 1);

    // coarse x mapping for the three full-res columns
    float pxc0 = fminf((float)ixm * SXC, 959.0f);
    float pxc1 = fminf((float)x   * SXC, 959.0f);
    float pxc2 = fminf((float)ixp * SXC, 959.0f);
    float f0 = floorf(pxc0), f1 = floorf(pxc1), f2 = floorf(pxc2);
    int c0 = (int)f0;
    float fx0 = pxc0 - f0, fx1 = pxc1 - f1, fx2 = pxc2 - f2;
    bool lx1 = ((int)f1 > c0), lx2 = ((int)f2 > c0);   // 0/1 local column offset

    // coarse y mapping for the three full-res rows
    float pyc0 = fminf((float)jym * SYC, 539.0f);
    float pyc1 = fminf((float)y   * SYC, 539.0f);
    float pyc2 = fminf((float)jyp * SYC, 539.0f);
    float g0 = floorf(pyc0), g1 = floorf(pyc1), g2 = floorf(pyc2);
    int r0 = (int)g0;
    float fy0 = pyc0 - g0, fy1 = pyc1 - g1, fy2 = pyc2 - g2;
    bool ly1 = ((int)g1 > r0), ly2 = ((int)g2 > r0);

    // load coarse 3x3 (clamped)
    const float2* gs = g_gs + b * SH * SW;
    int cc1 = min(c0 + 1, SW - 1), cc2 = min(c0 + 2, SW - 1);
    int rr0 = r0, rr1 = min(r0 + 1, SH - 1), rr2 = min(r0 + 2, SH - 1);
    float2 c_[3][3];
    c_[0][0] = gs[rr0 * SW + c0]; c_[0][1] = gs[rr0 * SW + cc1]; c_[0][2] = gs[rr0 * SW + cc2];
    c_[1][0] = gs[rr1 * SW + c0]; c_[1][1] = gs[rr1 * SW + cc1]; c_[1][2] = gs[rr1 * SW + cc2];
    c_[2][0] = gs[rr2 * SW + c0]; c_[2][1] = gs[rr2 * SW + cc1]; c_[2][2] = gs[rr2 * SW + cc2];

    // horizontal interpolation at the three full-res columns, per coarse row
    float2 h[3][3];
    #pragma unroll
    for (int m = 0; m < 3; ++m) {
        // k=0: local col 0 by construction
        h[m][0] = make_float2(c_[m][0].x * (1.0f - fx0) + c_[m][1].x * fx0,
                              c_[m][0].y * (1.0f - fx0) + c_[m][1].y * fx0);
        float2 a1 = lx1 ? c_[m][1] : c_[m][0];
        float2 b1 = lx1 ? c_[m][2] : c_[m][1];
        h[m][1] = make_float2(a1.x * (1.0f - fx1) + b1.x * fx1,
                              a1.y * (1.0f - fx1) + b1.y * fx1);
        float2 a2 = lx2 ? c_[m][1] : c_[m][0];
        float2 b2 = lx2 ? c_[m][2] : c_[m][1];
        h[m][2] = make_float2(a2.x * (1.0f - fx2) + b2.x * fx2,
                              a2.y * (1.0f - fx2) + b2.y * fx2);
    }

    // vertical interpolation -> gf[3][3]
    float2 gf[3][3];
    #pragma unroll
    for (int k = 0; k < 3; ++k) {
        gf[0][k] = make_float2(h[0][k].x * (1.0f - fy0) + h[1][k].x * fy0,
                               h[0][k].y * (1.0f - fy0) + h[1][k].y * fy0);
        float2 a1 = ly1 ? h[1][k] : h[0][k];
        float2 b1 = ly1 ? h[2][k] : h[1][k];
        gf[1][k] = make_float2(a1.x * (1.0f - fy1) + b1.x * fy1,
                               a1.y * (1.0f - fy1) + b1.y * fy1);
        float2 a2 = ly2 ? h[1][k] : h[0][k];
        float2 b2 = ly2 ? h[2][k] : h[1][k];
        gf[2][k] = make_float2(a2.x * (1.0f - fy2) + b2.x * fy2,
                               a2.y * (1.0f - fy2) + b2.y * fy2);
    }

    // --- 6-iteration warp walk entirely in registers ---
    // gf index 0 -> (x-1 / y-1), 1 -> (x / y), 2 -> (x+1 / y+1), all clamped.
    // Positions stay within 0.6 px of (x,y), so i0 in {x-1, x}, j0 in {y-1, y}.
    float px = (float)x;
    float py = (float)y;

    #pragma unroll
    for (int it = 0; it < 6; ++it) {
        float sx = clampf(px, 0.0f, (float)(FW - 1));
        float sy = clampf(py, 0.0f, (float)(FH - 1));
        float x0f = floorf(sx), y0f = floorf(sy);
        int i0 = (int)x0f, j0 = (int)y0f;
        float wx = sx - x0f, wy = sy - y0f;
        bool di = (i0 >= x);
        bool dj = (j0 >= y);

        float2 ta0 = dj ? gf[1][0] : gf[0][0];
        float2 ta1 = dj ? gf[1][1] : gf[0][1];
        float2 ta2 = dj ? gf[1][2] : gf[0][2];
        float2 tb0 = dj ? gf[2][0] : gf[1][0];
        float2 tb1 = dj ? gf[2][1] : gf[1][1];
        float2 tb2 = dj ? gf[2][2] : gf[1][2];

        float2 v00 = di ? ta1 : ta0;
        float2 v01 = di ? ta2 : ta1;
        float2 v10 = di ? tb1 : tb0;
        float2 v11 = di ? tb2 : tb1;

        float dnx = (v00.x * (1.0f - wx) + v01.x * wx) * (1.0f - wy)
                  + (v10.x * (1.0f - wx) + v11.x * wx) * wy;
        float dny = (v00.y * (1.0f - wx) + v01.y * wx) * (1.0f - wy)
                  + (v10.y * (1.0f - wx) + v11.y * wx) * wy;

        float inv = 1.0f / (sqrtf(dnx * dnx + dny * dny) + 0.01f);
        px -= dnx * inv * STEPX;
        py -= dny * inv * STEPY;
    }

    // --- final image sample (shared weights across channels) ---
    float sx = clampf(px, 0.0f, (float)(FW - 1));
    float sy = clampf(py, 0.0f, (float)(FH - 1));
    float x0f = floorf(sx), y0f = floorf(sy);
    int i0 = (int)x0f, j0 = (int)y0f;
    int i1 = min(i0 + 1, FW - 1), j1 = min(j0 + 1, FH - 1);
    float wx = sx - x0f, wy = sy - y0f;
    float w00 = (1.0f - wx) * (1.0f - wy), w01 = wx * (1.0f - wy);
    float w10 = (1.0f - wx) * wy,          w11 = wx * wy;
    int o00 = j0 * FW + i0, o01 = j0 * FW + i1, o10 = j1 * FW + i0, o11 = j1 * FW + i1;

    const float* base = img + (size_t)b * 3 * FH * FW;
    float* obase = out + (size_t)b * 3 * FH * FW + (size_t)y * FW + x;
    #pragma unroll
    for (int c = 0; c < 3; ++c) {
        const float* plane = base + (size_t)c * FH * FW;
        float v = plane[o00] * w00 + plane[o01] * w01 + plane[o10] * w10 + plane[o11] * w11;
        obase[(size_t)c * FH * FW] = clampf(v, 0.0f, 1.0f);
    }
}

extern "C" void kernel_launch(void* const* d_in, const int* in_sizes, int n_in,
                              void* d_out, int out_size) {
    const float* img = (const float*)d_in[0];
    float* out = (float*)d_out;

    const int TB = 256;
    int gsmall = (NSMALL + TB - 1) / TB;
    int gbig   = (NBIG + TB - 1) / TB;

    k_luma_resize<<<gsmall, TB>>>(img);
    k_sobel<true><<<gsmall, TB>>>();     // sobel1 -> edge magnitude
    k_blur<<<gsmall, TB>>>();            // fused separable gaussian
    k_sobel<false><<<gsmall, TB>>>();    // sobel2 -> grad field (coarse)
    k_warp<<<gbig, TB>>>(img, out);      // fused upsample + walk + gather
}

// round 3
// speedup vs baseline: 1.2165x; 1.2165x over previous
#include <cuda_runtime.h>
#include <math.h>

// Problem geometry (fixed by the reference's setup_inputs)
#define NB 2
#define FH 1080
#define FW 1920
#define SH 540
#define SW 960

#define NSMALL (NB*SH*SW)
#define NBIG   (NB*FH*FW)

// Fractional pixel shifts: offset * (W-1)/W
#define S1 (959.0f/960.0f)     // sobel_offset=1.0, x, W=960
#define S2 (959.0f/1920.0f)    // kernel_offset=0.5, x, W=960
#define T1 (539.0f/540.0f)     // sobel_offset=1.0, y, H=540
#define T2 (539.0f/1080.0f)    // kernel_offset=0.5, y, H=540

// apply_warp step in pixel units: relstr * (dim-1)/dim, relstr = 0.1
#define STEPX (0.1f * 1919.0f/1920.0f)
#define STEPY (0.1f * 1079.0f/1080.0f)

// coarse<->full mapping (align_corners)
#define SXC (959.0f/1919.0f)
#define SYC (539.0f/1079.0f)

// Gaussian sigma=1.0, ks=5
#define GW0 0.05448868454964295f
#define GW1 0.24420134200323332f
#define GW2 0.4026199468942475f

// ---- scratch (static device memory; no allocations) ----
__device__ float  g_luma[NSMALL];
__device__ float  g_edge[NSMALL];
__device__ float  g_blur[NSMALL];
__device__ float2 g_gs  [NSMALL];
__device__ float2 g_gf  [NBIG];

__device__ __forceinline__ float clampf(float v, float lo, float hi) {
    return fminf(fmaxf(v, lo), hi);
}

// ---- 1. fused luma + bilinear resize 1080x1920 -> 540x960 ----
__global__ void k_luma_resize(const float* __restrict__ img) {
    int idx = blockIdx.x * blockDim.x + threadIdx.x;
    if (idx >= NSMALL) return;
    int x = idx % SW;
    int y = (idx / SW) % SH;
    int b = idx / (SW * SH);

    float px = clampf((float)x * (1919.0f / 959.0f), 0.0f, 1919.0f);
    float py = clampf((float)y * (1079.0f / 539.0f), 0.0f, 1079.0f);
    float x0f = floorf(px), y0f = floorf(py);
    int i0 = (int)x0f, j0 = (int)y0f;
    int i1 = min(i0 + 1, FW - 1), j1 = min(j0 + 1, FH - 1);
    float wx = px - x0f, wy = py - y0f;

    const float* r = img + (size_t)b * 3 * FH * FW;
    const float* g = r + FH * FW;
    const float* bb = g + FH * FW;

    int o00 = j0 * FW + i0, o01 = j0 * FW + i1, o10 = j1 * FW + i0, o11 = j1 * FW + i1;
    float v00 = 0.299f * r[o00] + 0.587f * g[o00] + 0.114f * bb[o00];
    float v01 = 0.299f * r[o01] + 0.587f * g[o01] + 0.114f * bb[o01];
    float v10 = 0.299f * r[o10] + 0.587f * g[o10] + 0.114f * bb[o10];
    float v11 = 0.299f * r[o11] + 0.587f * g[o11] + 0.114f * bb[o11];

    g_luma[idx] = (v00 * (1.0f - wx) + v01 * wx) * (1.0f - wy)
                + (v10 * (1.0f - wx) + v11 * wx) * wy;
}

// sobel_x for one row given 3 clamped taps (L=clamp(x-1), C=x, R=clamp(x+1)).
// Interior formulas are exact at borders: clamped taps coincide and the
// degenerate weight is 0.
__device__ __forceinline__ float2 sobelx_row(float L, float C, float R, float s, int x, int W) {
    float xs = fmaxf((float)x - s, 0.0f);
    float wl = xs - floorf(xs);
    float l = L * (1.0f - wl) + C * wl;
    float xs2 = fminf((float)x + s, (float)(W - 1));
    float wr = xs2 - floorf(xs2);
    float r = C * (1.0f - wr) + R * wr;
    return make_float2(r - l, l + 2.0f * C + r);
}

// ---- 2/4. fused sobel_x + sobel_y over a 3x3 clamped footprint ----
template<bool MAG>
__global__ void k_sobel() {
    int idx = blockIdx.x * blockDim.x + threadIdx.x;
    if (idx >= NSMALL) return;
    const float* src = MAG ? g_luma : g_blur;
    const float s = MAG ? S1 : S2;
    const float t = MAG ? T1 : T2;

    int x = idx % SW;
    int y = (idx / SW) % SH;
    int b = idx / (SW * SH);
    const float* plane = src + b * SH * SW;

    int xm = max(x - 1, 0), xp = min(x + 1, SW - 1);
    int ym = max(y - 1, 0), yp = min(y + 1, SH - 1);

    const float* r0 = plane + ym * SW;
    const float* r1 = plane + y  * SW;
    const float* r2 = plane + yp * SW;

    float2 s0 = sobelx_row(r0[xm], r0[x], r0[xp], s, x, SW);
    float2 s1 = sobelx_row(r1[xm], r1[x], r1[xp], s, x, SW);
    float2 s2 = sobelx_row(r2[xm], r2[x], r2[xp], s, x, SW);

    float ys = fmaxf((float)y - t, 0.0f);
    float wt = ys - floorf(ys);
    float2 top = make_float2(s0.x * (1.0f - wt) + s1.x * wt,
                             s0.y * (1.0f - wt) + s1.y * wt);
    float ys2 = fminf((float)y + t, (float)(SH - 1));
    float wb = ys2 - floorf(ys2);
    float2 bot = make_float2(s1.x * (1.0f - wb) + s2.x * wb,
                             s1.y * (1.0f - wb) + s2.y * wb);

    float xg = (top.x + 2.0f * s1.x + bot.x) * 0.125f;
    float yg = (bot.y - top.y) * 0.125f;

    if (MAG) {
        float m2 = xg * xg + yg * yg;
        g_edge[idx] = __powf(m2, 0.35f);   // sqrt(.)^0.7 == (.)^0.35
    } else {
        g_gs[idx] = make_float2(xg, yg);
    }
}

// ---- 3. fused separable 5x5 gaussian, replicate padding ----
__global__ void k_blur() {
    int idx = blockIdx.x * blockDim.x + threadIdx.x;
    if (idx >= NSMALL) return;
    int x = idx % SW;
    int y = (idx / SW) % SH;
    int b = idx / (SW * SH);
    const float* plane = g_edge + b * SH * SW;

    int xs[5] = { max(x - 2, 0), max(x - 1, 0), x, min(x + 1, SW - 1), min(x + 2, SW - 1) };
    int yrow[5] = { max(y - 2, 0), max(y - 1, 0), y, min(y + 1, SH - 1), min(y + 2, SH - 1) };

    float h[5];
    #pragma unroll
    for (int m = 0; m < 5; ++m) {
        const float* row = plane + yrow[m] * SW;
        h[m] = GW0 * row[xs[0]] + GW1 * row[xs[1]] + GW2 * row[xs[2]]
             + GW1 * row[xs[3]] + GW0 * row[xs[4]];
    }
    g_blur[idx] = GW0 * h[0] + GW1 * h[1] + GW2 * h[2] + GW1 * h[3] + GW0 * h[4];
}

// ---- 5. bilinear upsample grad field 540x960 -> 1080x1920, 2 px/thread ----
__global__ void __launch_bounds__(256) k_upsample() {
    int t = blockIdx.x * blockDim.x + threadIdx.x;     // pair index
    if (t >= NBIG / 2) return;
    int xp = t % (FW / 2);
    int y  = (t / (FW / 2)) % FH;
    int b  = t / ((FW / 2) * FH);
    int x0 = 2 * xp;

    float py = fminf((float)y * SYC, (float)(SH - 1));
    float y0f = floorf(py);
    int j0 = (int)y0f, j1 = min(j0 + 1, SH - 1);
    float wy = py - y0f;

    const float2* p0 = g_gs + b * SH * SW + j0 * SW;
    const float2* p1 = g_gs + b * SH * SW + j1 * SW;

    float2 res[2];
    #pragma unroll
    for (int k = 0; k < 2; ++k) {
        float px = fminf((float)(x0 + k) * SXC, (float)(SW - 1));
        float x0f = floorf(px);
        int i0 = (int)x0f, i1 = min(i0 + 1, SW - 1);
        float wx = px - x0f;
        float2 v00 = p0[i0], v01 = p0[i1];
        float2 v10 = p1[i0], v11 = p1[i1];
        res[k].x = (v00.x * (1.0f - wx) + v01.x * wx) * (1.0f - wy)
                 + (v10.x * (1.0f - wx) + v11.x * wx) * wy;
        res[k].y = (v00.y * (1.0f - wx) + v01.y * wx) * (1.0f - wy)
                 + (v10.y * (1.0f - wx) + v11.y * wx) * wy;
    }
    // 16B store covering both pixels (x0 even -> 16B aligned)
    float4 pack = make_float4(res[0].x, res[0].y, res[1].x, res[1].y);
    *reinterpret_cast<float4*>(&g_gf[(size_t)b * FH * FW + (size_t)y * FW + x0]) = pack;
}

// ---- 6. warp walk + image gather, 2 px/thread (doubles MLP on dependent chain) ----
__global__ void __launch_bounds__(256) k_warp(const float* __restrict__ img,
                                              float* __restrict__ out) {
    int t = blockIdx.x * blockDim.x + threadIdx.x;     // pair index
    if (t >= NBIG / 2) return;
    int xp = t % (FW / 2);
    int y  = (t / (FW / 2)) % FH;
    int b  = t / ((FW / 2) * FH);
    int x0 = 2 * xp;

    const float2* gf = g_gf + (size_t)b * FH * FW;

    float px[2], py[2];
    px[0] = (float)x0;       py[0] = (float)y;
    px[1] = (float)(x0 + 1); py[1] = (float)y;

    #pragma unroll
    for (int it = 0; it < 6; ++it) {
        float2 v00[2], v01[2], v10[2], v11[2];
        float wx[2], wy[2];
        // issue all 8 loads before consuming (two independent chains)
        #pragma unroll
        for (int k = 0; k < 2; ++k) {
            float sx = clampf(px[k], 0.0f, (float)(FW - 1));
            float sy = clampf(py[k], 0.0f, (float)(FH - 1));
            float x0f = floorf(sx), y0f = floorf(sy);
            int i0 = (int)x0f, j0 = (int)y0f;
            int i1 = min(i0 + 1, FW - 1), j1 = min(j0 + 1, FH - 1);
            wx[k] = sx - x0f; wy[k] = sy - y0f;
            v00[k] = gf[j0 * FW + i0]; v01[k] = gf[j0 * FW + i1];
            v10[k] = gf[j1 * FW + i0]; v11[k] = gf[j1 * FW + i1];
        }
        #pragma unroll
        for (int k = 0; k < 2; ++k) {
            float dnx = (v00[k].x * (1.0f - wx[k]) + v01[k].x * wx[k]) * (1.0f - wy[k])
                      + (v10[k].x * (1.0f - wx[k]) + v11[k].x * wx[k]) * wy[k];
            float dny = (v00[k].y * (1.0f - wx[k]) + v01[k].y * wx[k]) * (1.0f - wy[k])
                      + (v10[k].y * (1.0f - wx[k]) + v11[k].y * wx[k]) * wy[k];
            float inv = __fdividef(1.0f, sqrtf(dnx * dnx + dny * dny) + 0.01f);
            px[k] -= dnx * inv * STEPX;
            py[k] -= dny * inv * STEPY;
        }
    }

    // final image sample (shared weights across channels), both pixels
    const float* base = img + (size_t)b * 3 * FH * FW;
    float* obase = out + (size_t)b * 3 * FH * FW + (size_t)y * FW + x0;

    int o00[2], o01[2], o10[2], o11[2];
    float w00[2], w01[2], w10[2], w11[2];
    #pragma unroll
    for (int k = 0; k < 2; ++k) {
        float sx = clampf(px[k], 0.0f, (float)(FW - 1));
        float sy = clampf(py[k], 0.0f, (float)(FH - 1));
        float x0f = floorf(sx), y0f = floorf(sy);
        int i0 = (int)x0f, j0 = (int)y0f;
        int i1 = min(i0 + 1, FW - 1), j1 = min(j0 + 1, FH - 1);
        float wx = sx - x0f, wy = sy - y0f;
        w00[k] = (1.0f - wx) * (1.0f - wy); w01[k] = wx * (1.0f - wy);
        w10[k] = (1.0f - wx) * wy;          w11[k] = wx * wy;
        o00[k] = j0 * FW + i0; o01[k] = j0 * FW + i1;
        o10[k] = j1 * FW + i0; o11[k] = j1 * FW + i1;
    }

    #pragma unroll
    for (int c = 0; c < 3; ++c) {
        const float* plane = base + (size_t)c * FH * FW;
        float2 v;
        v.x = clampf(plane[o00[0]] * w00[0] + plane[o01[0]] * w01[0]
                   + plane[o10[0]] * w10[0] + plane[o11[0]] * w11[0], 0.0f, 1.0f);
        v.y = clampf(plane[o00[1]] * w00[1] + plane[o01[1]] * w01[1]
                   + plane[o10[1]] * w10[1] + plane[o11[1]] * w11[1], 0.0f, 1.0f);
        *reinterpret_cast<float2*>(obase + (size_t)c * FH * FW) = v;   // 8B aligned (x0 even)
    }
}

extern "C" void kernel_launch(void* const* d_in, const int* in_sizes, int n_in,
                              void* d_out, int out_size) {
    const float* img = (const float*)d_in[0];
    float* out = (float*)d_out;

    const int TB = 256;
    int gsmall = (NSMALL + TB - 1) / TB;
    int gpair  = (NBIG / 2 + TB - 1) / TB;

    k_luma_resize<<<gsmall, TB>>>(img);
    k_sobel<true><<<gsmall, TB>>>();     // sobel1 -> edge magnitude
    k_blur<<<gsmall, TB>>>();            // fused separable gaussian
    k_sobel<false><<<gsmall, TB>>>();    // sobel2 -> grad field (coarse)
    k_upsample<<<gpair, TB>>>();         // materialize full-res grad field
    k_warp<<<gpair, TB>>>(img, out);     // 6-iter walk + gather, 2 px/thread
}